// round 1
// baseline (speedup 1.0000x reference)
#include <cuda_runtime.h>

// Derived problem constants
// x: [32, 256, 64, 64] f32; weight: [256, 256, 3, 3] f32; bias: [256] f32
// out: [32, 256, 1, 1] f32
// H_out = W_out = 128 -> spatial = 16384
#define B_   32
#define C_   256
#define O_   256
#define HW_  4096            // 64*64
#define BC_  (B_ * C_)       // 8192
#define CO_  (C_ * O_)       // 65536

// Scratch (no allocations allowed)
__device__ float4 g_stats[BC_];   // (T, R0, C0, x00) per (b,c)
__device__ float4 g_wcat[CO_];    // (Wsum, -Wkh0, -Wkw0, W00) per (c,o)

// ---------------------------------------------------------------------------
// Kernel 1: per-(b,c) image statistics. One block per (b,c), 256 threads,
// each thread loads 4 float4 (16 elements). 134 MB streaming read.
// ---------------------------------------------------------------------------
__global__ void __launch_bounds__(256) stats_kernel(const float* __restrict__ x) {
    const int bc = blockIdx.x;
    const float4* __restrict__ p4 =
        reinterpret_cast<const float4*>(x + (size_t)bc * HW_);
    const int t = threadIdx.x;

    float s = 0.f, r0 = 0.f, c0 = 0.f, v00 = 0.f;

    #pragma unroll
    for (int i = 0; i < 4; i++) {
        const int j = t + i * 256;        // float4 index 0..1023
        float4 v = p4[j];
        float vs = v.x + v.y + v.z + v.w;
        s += vs;
        if (j < 16)          r0 += vs;    // row 0 = first 64 elems = 16 vec4s
        if ((j & 15) == 0)   c0 += v.x;   // col 0 = element index % 64 == 0
        if (j == 0)          v00 = v.x;
    }

    // warp reduce (3 values)
    #pragma unroll
    for (int off = 16; off > 0; off >>= 1) {
        s  += __shfl_xor_sync(0xFFFFFFFFu, s,  off);
        r0 += __shfl_xor_sync(0xFFFFFFFFu, r0, off);
        c0 += __shfl_xor_sync(0xFFFFFFFFu, c0, off);
    }

    __shared__ float ss[8], sr[8], sc[8];
    __shared__ float sv00;
    const int warp = t >> 5, lane = t & 31;
    if (t == 0) sv00 = v00;
    if (lane == 0) { ss[warp] = s; sr[warp] = r0; sc[warp] = c0; }
    __syncthreads();

    if (warp == 0) {
        float fs = (lane < 8) ? ss[lane] : 0.f;
        float fr = (lane < 8) ? sr[lane] : 0.f;
        float fc = (lane < 8) ? sc[lane] : 0.f;
        #pragma unroll
        for (int off = 4; off > 0; off >>= 1) {
            fs += __shfl_xor_sync(0xFFFFFFFFu, fs, off);
            fr += __shfl_xor_sync(0xFFFFFFFFu, fr, off);
            fc += __shfl_xor_sync(0xFFFFFFFFu, fc, off);
        }
        if (lane == 0) g_stats[bc] = make_float4(fs, fr, fc, sv00);
    }
}

// ---------------------------------------------------------------------------
// Kernel 2: weight folding. One thread per (c,o): read 9 floats, emit
// (Wsum, -Wkh0, -Wkw0, W00). 2.4 MB read.
// ---------------------------------------------------------------------------
__global__ void __launch_bounds__(256) wprep_kernel(const float* __restrict__ w) {
    const int i = blockIdx.x * 256 + threadIdx.x;   // (c*256 + o)
    if (i >= CO_) return;
    const float* p = w + (size_t)i * 9;
    float w00 = p[0], w01 = p[1], w02 = p[2];
    float w10 = p[3], w11 = p[4], w12 = p[5];
    float w20 = p[6], w21 = p[7], w22 = p[8];
    float wsum = ((w00 + w01) + (w02 + w10)) + ((w11 + w12) + (w20 + w21)) + w22;
    float wkh0 = w00 + w01 + w02;   // kh == 0 row
    float wkw0 = w00 + w10 + w20;   // kw == 0 col
    g_wcat[i] = make_float4(wsum, -wkh0, -wkw0, w00);
}

// ---------------------------------------------------------------------------
// Kernel 3: micro-GEMM S[b,o] = sum_c dot4(A[b,c], Wcat[c,o]) + epilogue.
// One block per b (32 blocks), thread = output channel o.
// A tile (4 KB) in smem, Wcat columns read coalesced (warp reads 512B/row).
// ---------------------------------------------------------------------------
__global__ void __launch_bounds__(256) gemm_kernel(const float* __restrict__ bias,
                                                   float* __restrict__ out) {
    const int b = blockIdx.x;
    const int o = threadIdx.x;

    __shared__ float4 A[C_];
    A[o] = g_stats[b * C_ + o];
    __syncthreads();

    float acc = 0.f;
    #pragma unroll 8
    for (int c = 0; c < C_; c++) {
        float4 a = A[c];
        float4 w = g_wcat[c * O_ + o];
        acc = fmaf(a.x, w.x, acc);
        acc = fmaf(a.y, w.y, acc);
        acc = fmaf(a.z, w.z, acc);
        acc = fmaf(a.w, w.w, acc);
    }
    out[b * O_ + o] = 2.0f * (acc * (1.0f / 16384.0f) + bias[o]);
}

// ---------------------------------------------------------------------------
extern "C" void kernel_launch(void* const* d_in, const int* in_sizes, int n_in,
                              void* d_out, int out_size) {
    const float* x    = (const float*)d_in[0];
    const float* wgt  = (const float*)d_in[1];
    const float* bias = (const float*)d_in[2];
    float* out        = (float*)d_out;

    stats_kernel<<<BC_, 256>>>(x);
    wprep_kernel<<<CO_ / 256, 256>>>(wgt);
    gemm_kernel<<<B_, 256>>>(bias, out);
}